// round 12
// baseline (speedup 1.0000x reference)
#include <cuda_runtime.h>
#include <cstdint>

// KVGather: out[n,i,k,w,c] = r_weight[n,i,k] * kv[n, r_idx[n,i,k], w, c]
// N=16, P2=64, TOPK=8, W2=64, C_KV=512
//
// FINAL (R8 champion, reproducibility re-bench):
// 1.074 GiB compulsory write + ~75 MB kv read spill -> at the traffic floor;
// purely HBM-bound. 6631 GB/s (83.6% of 8 TB/s spec) achieved.
// Settled by A/B across R1-R11:
//  - 128-bit nc loads with createpolicy L2::evict_last hint (256-bit loads
//    serialize in L1tex; the hint buys ~1% DRAM util)
//  - __stcs 128-bit streaming stores (beats default policy and STG.256)
//  - 256-thread one-shot blocks, 2048 float4/block, 32768 blocks (beats
//    128-thr, tile-per-block, and persistent-grid variants)
//  - int64/int32 index-width detection fused in-kernel (saves a launch)

#define KVG_N     16
#define KVG_P2    64
#define KVG_TOPK  8
#define KVG_W2    64
#define KVG_CKV   512

#define NUM_TILES   (KVG_N * KVG_P2 * KVG_TOPK)      // 8192
#define TILE_F4     (KVG_W2 * KVG_CKV / 4)           // 8192 float4 per tile (128 KB)
#define F4_PER_THR  8
#define THREADS     256
#define F4_PER_BLK  (F4_PER_THR * THREADS)           // 2048
#define BLKS_PER_TILE (TILE_F4 / F4_PER_BLK)         // 4
#define GRID        (NUM_TILES * BLKS_PER_TILE)      // 32768

__device__ __forceinline__ float4 ldg_l2el(const float4* p, uint64_t pol) {
    float4 v;
    asm("ld.global.nc.L2::cache_hint.v4.f32 {%0,%1,%2,%3}, [%4], %5;"
        : "=f"(v.x), "=f"(v.y), "=f"(v.z), "=f"(v.w)
        : "l"(p), "l"(pol));
    return v;
}

__global__ __launch_bounds__(THREADS, 8)
void kvg_gather_kernel(const float4* __restrict__ kv,
                       const float*  __restrict__ r_weight,
                       const void*   __restrict__ r_idx,
                       float4*       __restrict__ out) {
    const int bid   = blockIdx.x;
    const int tile  = bid >> 2;            // BLKS_PER_TILE = 4
    const int chunk = bid & 3;
    const int n     = tile >> 9;           // / (P2*TOPK)

    // ---- int64-vs-int32 index-width detection, fused in-kernel ----
    // View r_idx as int32 words. int64 values in [0,64) -> every odd word 0.
    // int32 indices -> OR of 32 odd words nonzero w.p. 1-(1/64)^32.
    // Words [1..63] are in-bounds for both layouts; sectors are L2-hot.
    const int lane = threadIdx.x & 31;
    unsigned probe = ((const unsigned*)r_idx)[2 * lane + 1];
    unsigned odd_or = __reduce_or_sync(0xffffffffu, probe);
    const bool is64 = (odd_or == 0u);

    long long idx;
    if (is64) idx = ((const long long*)r_idx)[tile];
    else      idx = (long long)((const int*)r_idx)[tile];

    const float wt = r_weight[tile];

    // L2 evict-last policy for the hot kv read set.
    uint64_t pol;
    asm("createpolicy.fractional.L2::evict_last.b64 %0, 1.0;" : "=l"(pol));

    const float4* __restrict__ src =
        kv + ((long long)n * KVG_P2 + idx) * (long long)TILE_F4;
    float4* __restrict__ dst = out + (long long)tile * (long long)TILE_F4;

    const int base = chunk * F4_PER_BLK + threadIdx.x;

#pragma unroll
    for (int j = 0; j < F4_PER_THR; j++) {
        const int p = base + j * THREADS;
        float4 v = ldg_l2el(&src[p], pol);
        v.x *= wt; v.y *= wt; v.z *= wt; v.w *= wt;
        // Streaming store: evict-first write stream.
        __stcs(&dst[p], v);
    }
}

extern "C" void kernel_launch(void* const* d_in, const int* in_sizes, int n_in,
                              void* d_out, int out_size) {
    // metadata order: r_idx, r_weight, kv
    const void*  r_idx    = d_in[0];
    const float* r_weight = (const float*)d_in[1];
    const float4* kv      = (const float4*)d_in[2];
    float4* out           = (float4*)d_out;

    kvg_gather_kernel<<<GRID, THREADS>>>(kv, r_weight, r_idx, out);
}

// round 13
// speedup vs baseline: 1.3632x; 1.3632x over previous
#include <cuda_runtime.h>
#include <cstdint>

// KVGather: out[n,i,k,w,c] = r_weight[n,i,k] * kv[n, r_idx[n,i,k], w, c]
// N=16, P2=64, TOPK=8, W2=64, C_KV=512
//
// FINAL (R5 configuration — chosen for reproducibility):
// 1.074 GiB compulsory write + ~75 MB kv read spill -> at the traffic floor;
// purely HBM-bound at ~6567 GB/s (82.8%).
// Variance finding (R8 vs R12): the createpolicy/L2::cache_hint load path is
// bimodal (173 us ... 240 us, L1tex spikes to 83%); the plain __ldg path
// measured 174.9 us kernel in BOTH R1 and R5. Expected value favors plain.
// Settled by A/B across R1-R12:
//  - 128-bit __ldg loads (256-bit loads serialize in L1tex; policy-hinted
//    loads are fast-but-fragile)
//  - __stcs 128-bit streaming stores (beats default policy and STG.256)
//  - 256-thread one-shot blocks, 2048 float4/block, 32768 blocks (beats
//    128-thr, tile-per-block, and persistent-grid variants)
//  - int64/int32 index-width detection fused in-kernel (saves a launch)

#define KVG_N     16
#define KVG_P2    64
#define KVG_TOPK  8
#define KVG_W2    64
#define KVG_CKV   512

#define NUM_TILES   (KVG_N * KVG_P2 * KVG_TOPK)      // 8192
#define TILE_F4     (KVG_W2 * KVG_CKV / 4)           // 8192 float4 per tile (128 KB)
#define F4_PER_THR  8
#define THREADS     256
#define F4_PER_BLK  (F4_PER_THR * THREADS)           // 2048
#define BLKS_PER_TILE (TILE_F4 / F4_PER_BLK)         // 4
#define GRID        (NUM_TILES * BLKS_PER_TILE)      // 32768

__global__ __launch_bounds__(THREADS, 8)
void kvg_gather_kernel(const float4* __restrict__ kv,
                       const float*  __restrict__ r_weight,
                       const void*   __restrict__ r_idx,
                       float4*       __restrict__ out) {
    const int bid   = blockIdx.x;
    const int tile  = bid >> 2;            // BLKS_PER_TILE = 4
    const int chunk = bid & 3;
    const int n     = tile >> 9;           // / (P2*TOPK)

    // ---- int64-vs-int32 index-width detection, fused in-kernel ----
    // View r_idx as int32 words. int64 values in [0,64) -> every odd word 0.
    // int32 indices -> OR of 32 odd words nonzero w.p. 1-(1/64)^32.
    // Words [1..63] are in-bounds for both layouts; sectors are L2-hot.
    const int lane = threadIdx.x & 31;
    unsigned probe = ((const unsigned*)r_idx)[2 * lane + 1];
    unsigned odd_or = __reduce_or_sync(0xffffffffu, probe);
    const bool is64 = (odd_or == 0u);

    long long idx;
    if (is64) idx = ((const long long*)r_idx)[tile];
    else      idx = (long long)((const int*)r_idx)[tile];

    const float wt = r_weight[tile];

    const float4* __restrict__ src =
        kv + ((long long)n * KVG_P2 + idx) * (long long)TILE_F4;
    float4* __restrict__ dst = out + (long long)tile * (long long)TILE_F4;

    const int base = chunk * F4_PER_BLK + threadIdx.x;

#pragma unroll
    for (int j = 0; j < F4_PER_THR; j++) {
        const int p = base + j * THREADS;
        float4 v = __ldg(&src[p]);
        v.x *= wt; v.y *= wt; v.z *= wt; v.w *= wt;
        // Streaming store: evict-first write stream keeps the hot kv read
        // set resident in L2.
        __stcs(&dst[p], v);
    }
}

extern "C" void kernel_launch(void* const* d_in, const int* in_sizes, int n_in,
                              void* d_out, int out_size) {
    // metadata order: r_idx, r_weight, kv
    const void*  r_idx    = d_in[0];
    const float* r_weight = (const float*)d_in[1];
    const float4* kv      = (const float4*)d_in[2];
    float4* out           = (float4*)d_out;

    kvg_gather_kernel<<<GRID, THREADS>>>(kv, r_weight, r_idx, out);
}

// round 14
// speedup vs baseline: 1.3664x; 1.0024x over previous
#include <cuda_runtime.h>
#include <cstdint>

// KVGather: out[n,i,k,w,c] = r_weight[n,i,k] * kv[n, r_idx[n,i,k], w, c]
// N=16, P2=64, TOPK=8, W2=64, C_KV=512
//
// FINAL — stable champion (kernel 174.1-174.9 us across 3 runs, 6590-6630
// GB/s, DRAM 83%). At the compulsory traffic floor (1.074 GiB write +
// ~75 MB read spill); purely HBM-write-bound, ~95% of B300's measured LTS
// ceiling for this mix.
//
// Settled by A/B across 13 rounds:
//  - 128-bit __ldg loads: 256-bit loads serialize in L1tex (-37%);
//    createpolicy/L2::cache_hint loads are bimodal (173us...240us) -> plain.
//  - __stcs 128-bit streaming stores: beats default policy (+1.3%) and
//    STG.256 (neutral). Evict-first write stream preserves L2 for kv reads.
//  - 256-thread one-shot blocks, 2048 float4 each (32768 blocks): beats
//    128-thread, tile-per-block (-5%), and persistent-grid (-39%) variants.
//    HW scheduler pipelines fresh blocks' loads against draining stores.
//  - int64/int32 index-width detection fused in-kernel (saves ~5us launch).

#define KVG_N     16
#define KVG_P2    64
#define KVG_TOPK  8
#define KVG_W2    64
#define KVG_CKV   512

#define NUM_TILES   (KVG_N * KVG_P2 * KVG_TOPK)      // 8192
#define TILE_F4     (KVG_W2 * KVG_CKV / 4)           // 8192 float4 per tile (128 KB)
#define F4_PER_THR  8
#define THREADS     256
#define F4_PER_BLK  (F4_PER_THR * THREADS)           // 2048
#define BLKS_PER_TILE (TILE_F4 / F4_PER_BLK)         // 4
#define GRID        (NUM_TILES * BLKS_PER_TILE)      // 32768

__global__ __launch_bounds__(THREADS, 8)
void kvg_gather_kernel(const float4* __restrict__ kv,
                       const float*  __restrict__ r_weight,
                       const void*   __restrict__ r_idx,
                       float4*       __restrict__ out) {
    const int bid   = blockIdx.x;
    const int tile  = bid >> 2;            // BLKS_PER_TILE = 4
    const int chunk = bid & 3;
    const int n     = tile >> 9;           // / (P2*TOPK)

    // ---- int64-vs-int32 index-width detection, fused in-kernel ----
    // View r_idx as int32 words. int64 values in [0,64) -> every odd word 0.
    // int32 indices -> OR of 32 odd words nonzero w.p. 1-(1/64)^32.
    // Words [1..63] are in-bounds for both layouts; sectors are L2-hot.
    const int lane = threadIdx.x & 31;
    unsigned probe = ((const unsigned*)r_idx)[2 * lane + 1];
    unsigned odd_or = __reduce_or_sync(0xffffffffu, probe);
    const bool is64 = (odd_or == 0u);

    long long idx;
    if (is64) idx = ((const long long*)r_idx)[tile];
    else      idx = (long long)((const int*)r_idx)[tile];

    const float wt = r_weight[tile];

    const float4* __restrict__ src =
        kv + ((long long)n * KVG_P2 + idx) * (long long)TILE_F4;
    float4* __restrict__ dst = out + (long long)tile * (long long)TILE_F4;

    const int base = chunk * F4_PER_BLK + threadIdx.x;

#pragma unroll
    for (int j = 0; j < F4_PER_THR; j++) {
        const int p = base + j * THREADS;
        float4 v = __ldg(&src[p]);
        v.x *= wt; v.y *= wt; v.z *= wt; v.w *= wt;
        // Streaming store: evict-first write stream keeps the hot kv read
        // set resident in L2.
        __stcs(&dst[p], v);
    }
}

extern "C" void kernel_launch(void* const* d_in, const int* in_sizes, int n_in,
                              void* d_out, int out_size) {
    // metadata order: r_idx, r_weight, kv
    const void*  r_idx    = d_in[0];
    const float* r_weight = (const float*)d_in[1];
    const float4* kv      = (const float4*)d_in[2];
    float4* out           = (float4*)d_out;

    kvg_gather_kernel<<<GRID, THREADS>>>(kv, r_weight, r_idx, out);
}